// round 3
// baseline (speedup 1.0000x reference)
#include <cuda_runtime.h>
#include <cuda_bf16.h>
#include <math.h>
#include <stdint.h>

#define BATCH    512
#define NCLS     100000
#define DIM      512
#define CM       64                 /* classes per CTA */
#define MT2      1563               /* ceil(NCLS/64) */
#define S_SCALE  30.0f
#define SHIFT    30.0f
#define N_U      110.0f
#define N_L      10.0f
#define M_U      1.0f
#define M_L      0.1f
#define LAMBDA_G 35.0f
#define PI_F     3.14159265358979323846f

#define LDT      72                 /* smem pitch (bf16 elems): 144B, conflict-free */
#define BKK      64                 /* K per chunk */
#define NCH      (DIM / BKK)        /* 8 */

/* dynamic smem layout (bytes) */
#define OFF_SB    0                         /* [2][512*LDT] bf16 = 147456 */
#define OFF_SA    147456                    /* [2][64*LDT]  bf16 = 18432  */
#define OFF_INVN  165888                    /* float[64]          = 256   */
#define OFF_RSUM  166144                    /* float[2][512]      = 4096  */
#define OFF_RMAX  170240                    /* ull[2][512]        = 8192  */
#define OFF_MP    178432                    /* float4[512]        = 8192  */
#define OFF_LAB   186624                    /* int[512]           = 2048  */
#define SMEM_BYTES 188672

// ---------------- static device scratch (small) ----------------
__device__ __nv_bfloat16 g_xn[BATCH * DIM];          // normalized x, bf16 (512 KB)
__device__ float4 g_mp[BATCH];                       // {cos_m, sin_m, th, mm}
__device__ float  g_xnorm_cl[BATCH];
__device__ float  g_tlogit[BATCH];
__device__ int    g_labels[BATCH];
__device__ float  g_sum_part[(size_t)MT2 * BATCH];            // 3.2 MB
__device__ unsigned long long g_max_part[(size_t)MT2 * BATCH]; // 6.4 MB
__device__ float  g_ce[BATCH], g_corr[BATCH], g_gt[BATCH];

// monotonic float -> uint encode for packed max/argmax
__device__ __forceinline__ unsigned int fenc(float f) {
    unsigned int u = __float_as_uint(f);
    return (u & 0x80000000u) ? ~u : (u | 0x80000000u);
}

__device__ __forceinline__ void cpa16(uint32_t dst, const void* src) {
    asm volatile("cp.async.cg.shared.global [%0], [%1], 16;" :: "r"(dst), "l"(src));
}

// ---------------- label dtype detection + decode ----------------
__global__ void k_labels(const void* lab) {
    __shared__ int s_is64;
    int tid = threadIdx.x;
    if (tid == 0) s_is64 = 1;
    __syncthreads();
    if (tid < BATCH / 2) {
        long long v = ((const long long*)lab)[tid];
        if (v < 0 || v >= (long long)NCLS) s_is64 = 0;
    }
    __syncthreads();
    if (tid < BATCH) {
        int v;
        if (s_is64) v = (int)((const long long*)lab)[tid];
        else        v = ((const int*)lab)[tid];
        g_labels[tid] = v;
    }
}

// ---------------- x: norms, margin params, bf16 normalize ----------------
__global__ void k_prep_x(const float* __restrict__ x) {
    int row = blockIdx.x;
    int t = threadIdx.x;  // 128
    float4 v = ((const float4*)(x + (size_t)row * DIM))[t];
    float ss = v.x * v.x + v.y * v.y + v.z * v.z + v.w * v.w;
    #pragma unroll
    for (int o = 16; o; o >>= 1) ss += __shfl_xor_sync(0xffffffffu, ss, o);
    __shared__ float s[4];
    if ((t & 31) == 0) s[t >> 5] = ss;
    __syncthreads();
    float tot = s[0] + s[1] + s[2] + s[3];
    float nrm = sqrtf(tot);
    float inv = 1.0f / nrm;
    if (t == 0) {
        float a = fminf(fmaxf(nrm, N_L), N_U);
        float m = (M_U - M_L) / (N_U - N_L) * (a - N_L) + M_L;
        g_mp[row] = make_float4(cosf(m), sinf(m), cosf(PI_F - m), sinf(PI_F - m) * m);
        g_xnorm_cl[row] = a;
    }
    __nv_bfloat162* dst = (__nv_bfloat162*)(g_xn + (size_t)row * DIM);
    dst[2 * t]     = __floats2bfloat162_rn(v.x * inv, v.y * inv);
    dst[2 * t + 1] = __floats2bfloat162_rn(v.z * inv, v.w * inv);
}

// ---------------- fused GEMM: on-the-fly W norm + cosine + margin/softmax partials ----------------
// CTA: 64 classes x 512 batch, K=512 chunked by 64. 8 warps = 2(M) x 4(N);
// warp tile 32x128. W fp32 streamed once; ||W||^2 accumulated in-flight.
__global__ void __launch_bounds__(256, 1) k_gemm(const float* __restrict__ W) {
    extern __shared__ char smem[];
    __nv_bfloat16* sB = (__nv_bfloat16*)(smem + OFF_SB);
    __nv_bfloat16* sA = (__nv_bfloat16*)(smem + OFF_SA);
    float* s_invn = (float*)(smem + OFF_INVN);
    float* s_rsum = (float*)(smem + OFF_RSUM);
    unsigned long long* s_rmax = (unsigned long long*)(smem + OFF_RMAX);
    float4* s_mp = (float4*)(smem + OFF_MP);
    int* s_lab = (int*)(smem + OFF_LAB);

    int tid = threadIdx.x;
    int ctile = blockIdx.x;
    int cbase = ctile * CM;

    // per-sample params to smem
    s_mp[tid] = g_mp[tid]; s_mp[tid + 256] = g_mp[tid + 256];
    s_lab[tid] = g_labels[tid]; s_lab[tid + 256] = g_labels[tid + 256];

    uint32_t sb_u = (uint32_t)__cvta_generic_to_shared(sB);

    // ---- A (W) load geometry: 4 rows per thread, 16B fp32 chunk each ----
    int g4 = tid >> 4, ch4 = tid & 15;
    const float* aptr[4];
    int arow[4]; bool avalid[4];
    #pragma unroll
    for (int i = 0; i < 4; i++) {
        arow[i] = g4 + 16 * i;
        int R = cbase + arow[i];
        avalid[i] = (R < NCLS);
        aptr[i] = W + (size_t)(avalid[i] ? R : 0) * DIM + ch4 * 4;
    }
    float4 a4[4];
    float ssq[4] = {0.f, 0.f, 0.f, 0.f};

    int warp = tid >> 5, lane = tid & 31;
    int wm = warp & 1;        // M half
    int wn = warp >> 1;       // N quarter
    int g = lane >> 2, tg = lane & 3;

    float acc[2][16][4];
    #pragma unroll
    for (int mt = 0; mt < 2; mt++)
        #pragma unroll
        for (int nt = 0; nt < 16; nt++)
            #pragma unroll
            for (int e = 0; e < 4; e++) acc[mt][nt][e] = 0.0f;

    // ---- prologue: B chunk 0 via cp.async, A chunk 0 via regs ----
    {
        #pragma unroll
        for (int j = 0; j < 16; j++) {
            int idx = tid + j * 256;
            int row = idx >> 3, ch = idx & 7;
            cpa16(sb_u + (uint32_t)((row * LDT + ch * 8) * 2), g_xn + row * DIM + ch * 8);
        }
        asm volatile("cp.async.commit_group;");
        #pragma unroll
        for (int i = 0; i < 4; i++)
            a4[i] = avalid[i] ? *(const float4*)(aptr[i]) : make_float4(0.f, 0.f, 0.f, 0.f);
    }

    int cur = 0;
    #pragma unroll
    for (int kt = 0; kt < NCH; kt++) {
        asm volatile("cp.async.wait_group 0;" ::: "memory");
        // store A regs -> sA[cur], accumulate ||W row||^2
        {
            __nv_bfloat16* base = sA + cur * (CM * LDT);
            #pragma unroll
            for (int i = 0; i < 4; i++) {
                float4 v = a4[i];
                ssq[i] += v.x * v.x + v.y * v.y + v.z * v.z + v.w * v.w;
                __nv_bfloat162 p0 = __floats2bfloat162_rn(v.x, v.y);
                __nv_bfloat162 p1 = __floats2bfloat162_rn(v.z, v.w);
                uint2 u;
                u.x = *(uint32_t*)&p0; u.y = *(uint32_t*)&p1;
                *(uint2*)(base + arow[i] * LDT + ch4 * 4) = u;
            }
        }
        __syncthreads();

        if (kt + 1 < NCH) {
            int kk = (kt + 1) * BKK;
            uint32_t bbuf = sb_u + (uint32_t)((cur ^ 1) * (512 * LDT * 2));
            #pragma unroll
            for (int j = 0; j < 16; j++) {
                int idx = tid + j * 256;
                int row = idx >> 3, ch = idx & 7;
                cpa16(bbuf + (uint32_t)((row * LDT + ch * 8) * 2), g_xn + row * DIM + kk + ch * 8);
            }
            asm volatile("cp.async.commit_group;");
            #pragma unroll
            for (int i = 0; i < 4; i++)
                a4[i] = avalid[i] ? *(const float4*)(aptr[i] + kk) : make_float4(0.f, 0.f, 0.f, 0.f);
        }

        const __nv_bfloat16* A = sA + cur * (CM * LDT);
        const __nv_bfloat16* B = sB + cur * (512 * LDT);
        #pragma unroll
        for (int ks = 0; ks < BKK; ks += 16) {
            unsigned af[2][4];
            #pragma unroll
            for (int mt = 0; mt < 2; mt++) {
                int row = wm * 32 + mt * 16;
                af[mt][0] = *(const unsigned*)&A[(row + g) * LDT + ks + 2 * tg];
                af[mt][1] = *(const unsigned*)&A[(row + g + 8) * LDT + ks + 2 * tg];
                af[mt][2] = *(const unsigned*)&A[(row + g) * LDT + ks + 8 + 2 * tg];
                af[mt][3] = *(const unsigned*)&A[(row + g + 8) * LDT + ks + 8 + 2 * tg];
            }
            #pragma unroll
            for (int nt = 0; nt < 16; nt++) {
                int col = wn * 128 + nt * 8 + g;
                unsigned b0 = *(const unsigned*)&B[col * LDT + ks + 2 * tg];
                unsigned b1 = *(const unsigned*)&B[col * LDT + ks + 8 + 2 * tg];
                #pragma unroll
                for (int mt = 0; mt < 2; mt++) {
                    asm volatile(
                        "mma.sync.aligned.m16n8k16.row.col.f32.bf16.bf16.f32 "
                        "{%0,%1,%2,%3},{%4,%5,%6,%7},{%8,%9},{%0,%1,%2,%3};\n"
                        : "+f"(acc[mt][nt][0]), "+f"(acc[mt][nt][1]),
                          "+f"(acc[mt][nt][2]), "+f"(acc[mt][nt][3])
                        : "r"(af[mt][0]), "r"(af[mt][1]), "r"(af[mt][2]), "r"(af[mt][3]),
                          "r"(b0), "r"(b1));
                }
            }
        }
        cur ^= 1;
    }

    // ---- finalize ||W||: reduce ssq across the 16 threads sharing each row ----
    #pragma unroll
    for (int i = 0; i < 4; i++) {
        float s = ssq[i];
        #pragma unroll
        for (int o = 1; o < 16; o <<= 1) s += __shfl_xor_sync(0xffffffffu, s, o);
        if ((tid & 15) == 0)
            s_invn[g4 + 16 * i] = (s > 0.f) ? rsqrtf(s) : 0.f;
    }
    __syncthreads();

    float invn_r[2][2];
    #pragma unroll
    for (int mt = 0; mt < 2; mt++)
        #pragma unroll
        for (int hi = 0; hi < 2; hi++)
            invn_r[mt][hi] = s_invn[wm * 32 + mt * 16 + g + hi * 8];

    // ---- fused epilogue: cosine = dot * invn; margin@target; exp-sum; argmax ----
    #pragma unroll
    for (int nt = 0; nt < 16; nt++) {
        #pragma unroll
        for (int lo = 0; lo < 2; lo++) {
            int lcol = wn * 128 + nt * 8 + 2 * tg + lo;
            float4 mp = s_mp[lcol];
            int lab = s_lab[lcol];
            float lsum = 0.0f;
            unsigned long long lmax = 0ull;
            #pragma unroll
            for (int mt = 0; mt < 2; mt++) {
                #pragma unroll
                for (int hi = 0; hi < 2; hi++) {
                    int c = cbase + wm * 32 + mt * 16 + g + hi * 8;
                    if (c < NCLS) {
                        float v = acc[mt][nt][hi * 2 + lo] * invn_r[mt][hi];
                        float logit;
                        if (c == lab) {
                            float sine = sqrtf(fmaxf(0.0f, 1.0f - v * v));
                            float phi = v * mp.x - sine * mp.y;
                            logit = ((v - mp.z > 0.0f) ? phi : (v - mp.w)) * S_SCALE;
                            g_tlogit[lcol] = logit;
                        } else {
                            logit = v * S_SCALE;
                        }
                        lsum += __expf(logit - SHIFT);
                        unsigned long long p =
                            ((unsigned long long)fenc(logit) << 32) |
                            (unsigned long long)(0xFFFFFFFFu - (unsigned)c);
                        lmax = (p > lmax) ? p : lmax;
                    }
                }
            }
            #pragma unroll
            for (int off = 4; off < 32; off <<= 1) {
                lsum += __shfl_xor_sync(0xffffffffu, lsum, off);
                unsigned long long o = __shfl_xor_sync(0xffffffffu, lmax, off);
                lmax = (o > lmax) ? o : lmax;
            }
            if (g == 0) {
                s_rsum[wm * 512 + lcol] = lsum;
                s_rmax[wm * 512 + lcol] = lmax;
            }
        }
    }
    __syncthreads();
    #pragma unroll
    for (int r = 0; r < 2; r++) {
        int col = tid + r * 256;
        g_sum_part[(size_t)ctile * BATCH + col] = s_rsum[col] + s_rsum[512 + col];
        unsigned long long a = s_rmax[col], b = s_rmax[512 + col];
        g_max_part[(size_t)ctile * BATCH + col] = (a > b) ? a : b;
    }
}

// ---------------- per-sample reduction over class tiles ----------------
__global__ void k_reduce() {
    int b = blockIdx.x, t = threadIdx.x;  // 128 threads
    float sum = 0.0f;
    unsigned long long mx = 0ull;
    for (int tt = t; tt < MT2; tt += 128) {
        sum += g_sum_part[(size_t)tt * BATCH + b];
        unsigned long long p = g_max_part[(size_t)tt * BATCH + b];
        mx = (p > mx) ? p : mx;
    }
    __shared__ float ss[128];
    __shared__ unsigned long long sm_[128];
    ss[t] = sum; sm_[t] = mx;
    __syncthreads();
    for (int o = 64; o; o >>= 1) {
        if (t < o) {
            ss[t] += ss[t + o];
            if (sm_[t + o] > sm_[t]) sm_[t] = sm_[t + o];
        }
        __syncthreads();
    }
    if (t == 0) {
        float lse = logf(ss[0]) + SHIFT;
        g_ce[b] = lse - g_tlogit[b];
        int pred = (int)(0xFFFFFFFFu - (unsigned)(sm_[0] & 0xFFFFFFFFull));
        g_corr[b] = (pred == g_labels[b]) ? 1.0f : 0.0f;
        float a = g_xnorm_cl[b];
        g_gt[b] = a / (N_U * N_U) + 1.0f / a;
    }
}

// ---------------- final scalar outputs ----------------
__global__ void k_final(float* __restrict__ out, int out_size) {
    int b = threadIdx.x;  // 512
    __shared__ float s1[512], s2[512], s3[512];
    s1[b] = g_ce[b]; s2[b] = g_corr[b]; s3[b] = g_gt[b];
    __syncthreads();
    for (int o = 256; o; o >>= 1) {
        if (b < o) { s1[b] += s1[b + o]; s2[b] += s2[b + o]; s3[b] += s3[b + o]; }
        __syncthreads();
    }
    if (b == 0) {
        float loss = s1[0] / (float)BATCH + LAMBDA_G * (s3[0] / (float)BATCH);
        if (out_size >= 1) out[0] = loss;
        if (out_size >= 2) out[1] = s2[0] / (float)BATCH * 100.0f;
    }
    if (b >= 2 && b < out_size) out[b] = 0.0f;
}

extern "C" void kernel_launch(void* const* d_in, const int* in_sizes, int n_in,
                              void* d_out, int out_size) {
    const float* x = (const float*)d_in[0];
    const void* lab = d_in[1];
    const float* w = (const float*)d_in[2];
    (void)in_sizes; (void)n_in;

    cudaFuncSetAttribute(k_gemm, cudaFuncAttributeMaxDynamicSharedMemorySize, SMEM_BYTES);

    k_labels<<<1, 512>>>(lab);
    k_prep_x<<<BATCH, 128>>>(x);
    k_gemm<<<MT2, 256, SMEM_BYTES>>>(w);
    k_reduce<<<BATCH, 128>>>();
    k_final<<<1, 512>>>((float*)d_out, out_size);
}

// round 4
// speedup vs baseline: 1.6294x; 1.6294x over previous
#include <cuda_runtime.h>
#include <cuda_bf16.h>
#include <math.h>
#include <stdint.h>

#define BATCH    512
#define NCLS     100000
#define DIM      512
#define CM       64                 /* classes per CTA */
#define MT2      1563               /* ceil(NCLS/64) */
#define S_SCALE  30.0f
#define SHIFT    30.0f
#define N_U      110.0f
#define N_L      10.0f
#define M_U      1.0f
#define M_L      0.1f
#define LAMBDA_G 35.0f
#define PI_F     3.14159265358979323846f

#define LDT      72                 /* smem pitch (bf16 elems): 144B, conflict-free */
#define BKK      64                 /* K per chunk */
#define NCH      (DIM / BKK)        /* 8 */

/* dynamic smem layout (bytes) */
#define OFF_SB    0                         /* [2][512*LDT] bf16 = 147456 */
#define OFF_SA    147456                    /* [2][64*LDT]  bf16 = 18432  */
#define OFF_INVN  165888                    /* float[64]          = 256   */
#define OFF_RSUM  166144                    /* float[2][512]      = 4096  */
#define OFF_RMAX  170240                    /* ull[2][512]        = 8192  */
#define OFF_MP    178432                    /* float4[512]        = 8192  */
#define OFF_LAB   186624                    /* int[512]           = 2048  */
#define SMEM_BYTES 188672

// ---------------- static device scratch (small) ----------------
__device__ __nv_bfloat16 g_xn[BATCH * DIM];          // normalized x, bf16 (512 KB)
__device__ float4 g_mp[BATCH];                       // {cos_m, sin_m, th, mm}
__device__ float  g_xnorm_cl[BATCH];
__device__ float  g_tlogit[BATCH];
__device__ int    g_labels[BATCH];
__device__ float  g_sum_part[(size_t)MT2 * BATCH];             // 3.2 MB
__device__ unsigned long long g_max_part[(size_t)MT2 * BATCH]; // 6.4 MB
__device__ float  g_ce[BATCH], g_corr[BATCH], g_gt[BATCH];

// monotonic float -> uint encode for packed max/argmax
__device__ __forceinline__ unsigned int fenc(float f) {
    unsigned int u = __float_as_uint(f);
    return (u & 0x80000000u) ? ~u : (u | 0x80000000u);
}

__device__ __forceinline__ void cpa16(uint32_t dst, const void* src) {
    asm volatile("cp.async.cg.shared.global [%0], [%1], 16;" :: "r"(dst), "l"(src));
}

__device__ __forceinline__ void ldsm_x4(uint32_t addr, unsigned& r0, unsigned& r1,
                                        unsigned& r2, unsigned& r3) {
    asm volatile("ldmatrix.sync.aligned.m8n8.x4.shared.b16 {%0,%1,%2,%3}, [%4];"
                 : "=r"(r0), "=r"(r1), "=r"(r2), "=r"(r3) : "r"(addr));
}

// ---------------- label dtype detection + decode ----------------
__global__ void k_labels(const void* lab) {
    __shared__ int s_is64;
    int tid = threadIdx.x;
    if (tid == 0) s_is64 = 1;
    __syncthreads();
    if (tid < BATCH / 2) {
        long long v = ((const long long*)lab)[tid];
        if (v < 0 || v >= (long long)NCLS) s_is64 = 0;
    }
    __syncthreads();
    if (tid < BATCH) {
        int v;
        if (s_is64) v = (int)((const long long*)lab)[tid];
        else        v = ((const int*)lab)[tid];
        g_labels[tid] = v;
    }
}

// ---------------- x: norms, margin params, bf16 normalize ----------------
__global__ void k_prep_x(const float* __restrict__ x) {
    int row = blockIdx.x;
    int t = threadIdx.x;  // 128
    float4 v = ((const float4*)(x + (size_t)row * DIM))[t];
    float ss = v.x * v.x + v.y * v.y + v.z * v.z + v.w * v.w;
    #pragma unroll
    for (int o = 16; o; o >>= 1) ss += __shfl_xor_sync(0xffffffffu, ss, o);
    __shared__ float s[4];
    if ((t & 31) == 0) s[t >> 5] = ss;
    __syncthreads();
    float tot = s[0] + s[1] + s[2] + s[3];
    float nrm = sqrtf(tot);
    float inv = 1.0f / nrm;
    if (t == 0) {
        float a = fminf(fmaxf(nrm, N_L), N_U);
        float m = (M_U - M_L) / (N_U - N_L) * (a - N_L) + M_L;
        g_mp[row] = make_float4(cosf(m), sinf(m), cosf(PI_F - m), sinf(PI_F - m) * m);
        g_xnorm_cl[row] = a;
    }
    __nv_bfloat162* dst = (__nv_bfloat162*)(g_xn + (size_t)row * DIM);
    dst[2 * t]     = __floats2bfloat162_rn(v.x * inv, v.y * inv);
    dst[2 * t + 1] = __floats2bfloat162_rn(v.z * inv, v.w * inv);
}

// ---------------- fused GEMM: on-the-fly W norm + cosine + margin/softmax partials ----------------
// CTA: 64 classes x 512 batch, K=512 in 8 chunks of 64. 512 threads = 16 warps
// as 2(M) x 8(N); warp tile 32x64; ldmatrix fragment loads; cp.async double-buffer.
__global__ void __launch_bounds__(512, 1) k_gemm(const float* __restrict__ W) {
    extern __shared__ char smem[];
    __nv_bfloat16* sB = (__nv_bfloat16*)(smem + OFF_SB);
    __nv_bfloat16* sA = (__nv_bfloat16*)(smem + OFF_SA);
    float* s_invn = (float*)(smem + OFF_INVN);
    float* s_rsum = (float*)(smem + OFF_RSUM);
    unsigned long long* s_rmax = (unsigned long long*)(smem + OFF_RMAX);
    float4* s_mp = (float4*)(smem + OFF_MP);
    int* s_lab = (int*)(smem + OFF_LAB);

    int tid = threadIdx.x;
    int ctile = blockIdx.x;
    int cbase = ctile * CM;

    s_mp[tid] = g_mp[tid];
    s_lab[tid] = g_labels[tid];

    uint32_t sb_u = (uint32_t)__cvta_generic_to_shared(sB);
    uint32_t sa_u = (uint32_t)__cvta_generic_to_shared(sA);

    // ---- A (W) load geometry: 2 rows per thread, one 16B fp32 chunk each ----
    int g4 = tid >> 4, ch4 = tid & 15;       // g4: 0..31, ch4: 0..15
    const float* aptr[2];
    int arow[2]; bool avalid[2];
    #pragma unroll
    for (int i = 0; i < 2; i++) {
        arow[i] = g4 + 32 * i;
        int R = cbase + arow[i];
        avalid[i] = (R < NCLS);
        aptr[i] = W + (size_t)(avalid[i] ? R : 0) * DIM + ch4 * 4;
    }
    float4 a4[2];
    float ssq[2] = {0.f, 0.f};

    int warp = tid >> 5, lane = tid & 31;
    int wm = warp & 1;        // M half (0..1)
    int wn = warp >> 1;       // N eighth (0..7)
    int g = lane >> 2, tg = lane & 3;

    // ldmatrix per-thread source offsets (element units within a buffer)
    int a_lrow = wm * 32 + (lane & 7) + ((lane >> 3) & 1) * 8;   // + mt*16
    int a_lkb  = (lane >> 4) * 16;                                // byte offset in k
    int b_lrow = wn * 64 + (lane & 7) + (lane >> 4) * 8;          // + p*16
    int b_lkb  = ((lane >> 3) & 1) * 16;

    float acc[2][8][4];
    #pragma unroll
    for (int mt = 0; mt < 2; mt++)
        #pragma unroll
        for (int nt = 0; nt < 8; nt++)
            #pragma unroll
            for (int e = 0; e < 4; e++) acc[mt][nt][e] = 0.0f;

    // ---- prologue: B chunk 0 via cp.async, A chunk 0 into regs ----
    {
        #pragma unroll
        for (int j = 0; j < 8; j++) {
            int idx = tid + j * 512;
            int row = idx >> 3, ch = idx & 7;
            cpa16(sb_u + (uint32_t)((row * LDT + ch * 8) * 2), g_xn + row * DIM + ch * 8);
        }
        asm volatile("cp.async.commit_group;");
        #pragma unroll
        for (int i = 0; i < 2; i++)
            a4[i] = avalid[i] ? *(const float4*)(aptr[i]) : make_float4(0.f, 0.f, 0.f, 0.f);
    }

    int cur = 0;
    #pragma unroll
    for (int kt = 0; kt < NCH; kt++) {
        asm volatile("cp.async.wait_group 0;" ::: "memory");
        // store A regs -> sA[cur], accumulate ||W row||^2
        {
            __nv_bfloat16* base = sA + cur * (CM * LDT);
            #pragma unroll
            for (int i = 0; i < 2; i++) {
                float4 v = a4[i];
                ssq[i] += v.x * v.x + v.y * v.y + v.z * v.z + v.w * v.w;
                __nv_bfloat162 p0 = __floats2bfloat162_rn(v.x, v.y);
                __nv_bfloat162 p1 = __floats2bfloat162_rn(v.z, v.w);
                uint2 u;
                u.x = *(uint32_t*)&p0; u.y = *(uint32_t*)&p1;
                *(uint2*)(base + arow[i] * LDT + ch4 * 4) = u;
            }
        }
        __syncthreads();

        if (kt + 1 < NCH) {
            int kk = (kt + 1) * BKK;
            uint32_t bbuf = sb_u + (uint32_t)((cur ^ 1) * (512 * LDT * 2));
            #pragma unroll
            for (int j = 0; j < 8; j++) {
                int idx = tid + j * 512;
                int row = idx >> 3, ch = idx & 7;
                cpa16(bbuf + (uint32_t)((row * LDT + ch * 8) * 2), g_xn + row * DIM + kk + ch * 8);
            }
            asm volatile("cp.async.commit_group;");
            #pragma unroll
            for (int i = 0; i < 2; i++)
                a4[i] = avalid[i] ? *(const float4*)(aptr[i] + kk) : make_float4(0.f, 0.f, 0.f, 0.f);
        }

        uint32_t Abase = sa_u + (uint32_t)(cur * (CM * LDT) * 2);
        uint32_t Bbase = sb_u + (uint32_t)(cur * (512 * LDT) * 2);
        #pragma unroll
        for (int ks = 0; ks < BKK; ks += 16) {
            unsigned af[2][4];
            #pragma unroll
            for (int mt = 0; mt < 2; mt++)
                ldsm_x4(Abase + (uint32_t)(((a_lrow + mt * 16) * LDT) * 2 + ks * 2 + a_lkb),
                        af[mt][0], af[mt][1], af[mt][2], af[mt][3]);
            #pragma unroll
            for (int p = 0; p < 4; p++) {
                unsigned b0, b1, b2, b3;
                ldsm_x4(Bbase + (uint32_t)(((b_lrow + p * 16) * LDT) * 2 + ks * 2 + b_lkb),
                        b0, b1, b2, b3);
                #pragma unroll
                for (int mt = 0; mt < 2; mt++) {
                    asm volatile(
                        "mma.sync.aligned.m16n8k16.row.col.f32.bf16.bf16.f32 "
                        "{%0,%1,%2,%3},{%4,%5,%6,%7},{%8,%9},{%0,%1,%2,%3};\n"
                        : "+f"(acc[mt][2 * p][0]), "+f"(acc[mt][2 * p][1]),
                          "+f"(acc[mt][2 * p][2]), "+f"(acc[mt][2 * p][3])
                        : "r"(af[mt][0]), "r"(af[mt][1]), "r"(af[mt][2]), "r"(af[mt][3]),
                          "r"(b0), "r"(b1));
                    asm volatile(
                        "mma.sync.aligned.m16n8k16.row.col.f32.bf16.bf16.f32 "
                        "{%0,%1,%2,%3},{%4,%5,%6,%7},{%8,%9},{%0,%1,%2,%3};\n"
                        : "+f"(acc[mt][2 * p + 1][0]), "+f"(acc[mt][2 * p + 1][1]),
                          "+f"(acc[mt][2 * p + 1][2]), "+f"(acc[mt][2 * p + 1][3])
                        : "r"(af[mt][0]), "r"(af[mt][1]), "r"(af[mt][2]), "r"(af[mt][3]),
                          "r"(b2), "r"(b3));
                }
            }
        }
        cur ^= 1;
    }

    // ---- finalize ||W||: reduce ssq across the 16 threads sharing each row ----
    #pragma unroll
    for (int i = 0; i < 2; i++) {
        float s = ssq[i];
        #pragma unroll
        for (int o = 1; o < 16; o <<= 1) s += __shfl_xor_sync(0xffffffffu, s, o);
        if ((tid & 15) == 0)
            s_invn[g4 + 32 * i] = (s > 0.f) ? rsqrtf(s) : 0.f;
    }
    __syncthreads();

    float invn_r[2][2];
    #pragma unroll
    for (int mt = 0; mt < 2; mt++)
        #pragma unroll
        for (int hi = 0; hi < 2; hi++)
            invn_r[mt][hi] = s_invn[wm * 32 + mt * 16 + g + hi * 8];

    // ---- fused epilogue: cosine = dot * invn; margin@target; exp-sum; argmax ----
    #pragma unroll
    for (int nt = 0; nt < 8; nt++) {
        #pragma unroll
        for (int lo = 0; lo < 2; lo++) {
            int lcol = wn * 64 + nt * 8 + 2 * tg + lo;
            float4 mp = s_mp[lcol];
            int lab = s_lab[lcol];
            float lsum = 0.0f;
            unsigned long long lmax = 0ull;
            #pragma unroll
            for (int mt = 0; mt < 2; mt++) {
                #pragma unroll
                for (int hi = 0; hi < 2; hi++) {
                    int c = cbase + wm * 32 + mt * 16 + g + hi * 8;
                    if (c < NCLS) {
                        float v = acc[mt][nt][hi * 2 + lo] * invn_r[mt][hi];
                        float logit;
                        if (c == lab) {
                            float sine = sqrtf(fmaxf(0.0f, 1.0f - v * v));
                            float phi = v * mp.x - sine * mp.y;
                            logit = ((v - mp.z > 0.0f) ? phi : (v - mp.w)) * S_SCALE;
                            g_tlogit[lcol] = logit;
                        } else {
                            logit = v * S_SCALE;
                        }
                        lsum += __expf(logit - SHIFT);
                        unsigned long long p =
                            ((unsigned long long)fenc(logit) << 32) |
                            (unsigned long long)(0xFFFFFFFFu - (unsigned)c);
                        lmax = (p > lmax) ? p : lmax;
                    }
                }
            }
            #pragma unroll
            for (int off = 4; off < 32; off <<= 1) {
                lsum += __shfl_xor_sync(0xffffffffu, lsum, off);
                unsigned long long o = __shfl_xor_sync(0xffffffffu, lmax, off);
                lmax = (o > lmax) ? o : lmax;
            }
            if (g == 0) {
                s_rsum[wm * 512 + lcol] = lsum;
                s_rmax[wm * 512 + lcol] = lmax;
            }
        }
    }
    __syncthreads();
    {
        int col = tid;
        g_sum_part[(size_t)ctile * BATCH + col] = s_rsum[col] + s_rsum[512 + col];
        unsigned long long a = s_rmax[col], b = s_rmax[512 + col];
        g_max_part[(size_t)ctile * BATCH + col] = (a > b) ? a : b;
    }
}

// ---------------- per-sample reduction over class tiles ----------------
__global__ void k_reduce() {
    int b = blockIdx.x, t = threadIdx.x;  // 128 threads
    float sum = 0.0f;
    unsigned long long mx = 0ull;
    for (int tt = t; tt < MT2; tt += 128) {
        sum += g_sum_part[(size_t)tt * BATCH + b];
        unsigned long long p = g_max_part[(size_t)tt * BATCH + b];
        mx = (p > mx) ? p : mx;
    }
    __shared__ float ss[128];
    __shared__ unsigned long long sm_[128];
    ss[t] = sum; sm_[t] = mx;
    __syncthreads();
    for (int o = 64; o; o >>= 1) {
        if (t < o) {
            ss[t] += ss[t + o];
            if (sm_[t + o] > sm_[t]) sm_[t] = sm_[t + o];
        }
        __syncthreads();
    }
    if (t == 0) {
        float lse = logf(ss[0]) + SHIFT;
        g_ce[b] = lse - g_tlogit[b];
        int pred = (int)(0xFFFFFFFFu - (unsigned)(sm_[0] & 0xFFFFFFFFull));
        g_corr[b] = (pred == g_labels[b]) ? 1.0f : 0.0f;
        float a = g_xnorm_cl[b];
        g_gt[b] = a / (N_U * N_U) + 1.0f / a;
    }
}

// ---------------- final scalar outputs ----------------
__global__ void k_final(float* __restrict__ out, int out_size) {
    int b = threadIdx.x;  // 512
    __shared__ float s1[512], s2[512], s3[512];
    s1[b] = g_ce[b]; s2[b] = g_corr[b]; s3[b] = g_gt[b];
    __syncthreads();
    for (int o = 256; o; o >>= 1) {
        if (b < o) { s1[b] += s1[b + o]; s2[b] += s2[b + o]; s3[b] += s3[b + o]; }
        __syncthreads();
    }
    if (b == 0) {
        float loss = s1[0] / (float)BATCH + LAMBDA_G * (s3[0] / (float)BATCH);
        if (out_size >= 1) out[0] = loss;
        if (out_size >= 2) out[1] = s2[0] / (float)BATCH * 100.0f;
    }
    if (b >= 2 && b < out_size) out[b] = 0.0f;
}

extern "C" void kernel_launch(void* const* d_in, const int* in_sizes, int n_in,
                              void* d_out, int out_size) {
    const float* x = (const float*)d_in[0];
    const void* lab = d_in[1];
    const float* w = (const float*)d_in[2];
    (void)in_sizes; (void)n_in;

    cudaFuncSetAttribute(k_gemm, cudaFuncAttributeMaxDynamicSharedMemorySize, SMEM_BYTES);

    k_labels<<<1, 512>>>(lab);
    k_prep_x<<<BATCH, 128>>>(x);
    k_gemm<<<MT2, 512, SMEM_BYTES>>>(w);
    k_reduce<<<BATCH, 128>>>();
    k_final<<<1, 512>>>((float*)d_out, out_size);
}

// round 7
// speedup vs baseline: 1.8253x; 1.1202x over previous
#include <cuda_runtime.h>
#include <cuda_bf16.h>
#include <math.h>
#include <stdint.h>

#define BATCH    512
#define NCLS     100000
#define DIM      512
#define CM       64                 /* classes per CTA */
#define NT       1563               /* ceil(NCLS/64) */
#define BKK      128                /* K per chunk (fp8: 128 bytes per row) */
#define NCH      (DIM / BKK)        /* 4 */
#define S_SCALE  30.0f
#define SHIFT    30.0f
#define N_U      110.0f
#define N_L      10.0f
#define M_U      1.0f
#define M_L      0.1f
#define LAMBDA_G 35.0f
#define PI_F     3.14159265358979323846f
#define WSC      64.0f              /* W pre-scale before e4m3 (clears subnormals) */

#define PITCHB   144                /* smem row pitch bytes: 128 + 16 pad, conflict-free */

/* dynamic smem layout (bytes) */
#define OFF_SX    0                          /* 2 x 512 x 144 = 147456 */
#define OFF_SW    147456                     /* 2 x  64 x 144 = 18432  */
#define OFF_INVN  165888                     /* float[64]     = 256    */
#define OFF_RSUM  166144                     /* float[2][512] = 4096   */
#define OFF_RMAX  170240                     /* ull[2][512]   = 8192   */
#define OFF_LAB   178432                     /* int[512]      = 2048   */
#define OFF_TL    180480                     /* float[512]    = 2048   */
#define SMEM_BYTES 182528

// ---------------- static device scratch ----------------
__device__ uint8_t g_xq[BATCH * DIM];        // x-hat, e4m3 (256 KB)
__device__ float   g_xnf[BATCH * DIM];       // x-hat, fp32 (1 MB, for exact target dot)
__device__ float4  g_mp[BATCH];              // {cos_m, sin_m, th, mm}
__device__ float   g_xnorm_cl[BATCH];
__device__ float   g_tlogit[BATCH];
__device__ int     g_labels[BATCH];
__device__ float   g_sumB[BATCH];
__device__ unsigned long long g_maxB[BATCH];

__device__ __forceinline__ unsigned int fenc(float f) {
    unsigned int u = __float_as_uint(f);
    return (u & 0x80000000u) ? ~u : (u | 0x80000000u);
}

__device__ __forceinline__ unsigned short cvt_e4m3x2(float hi, float lo) {
    unsigned short r;
    asm("cvt.rn.satfinite.e4m3x2.f32 %0, %1, %2;" : "=h"(r) : "f"(hi), "f"(lo));
    return r;  // low byte = lo, high byte = hi
}

__device__ __forceinline__ void cpa16(uint32_t dst, const void* src) {
    asm volatile("cp.async.cg.shared.global [%0], [%1], 16;" :: "r"(dst), "l"(src));
}

__device__ __forceinline__ void ldsm_x4(uint32_t addr, unsigned& r0, unsigned& r1,
                                        unsigned& r2, unsigned& r3) {
    asm volatile("ldmatrix.sync.aligned.m8n8.x4.shared.b16 {%0,%1,%2,%3}, [%4];"
                 : "=r"(r0), "=r"(r1), "=r"(r2), "=r"(r3) : "r"(addr));
}

// ---------------- label dtype detection + decode ----------------
__global__ void k_labels(const void* lab) {
    __shared__ int s_is64;
    int tid = threadIdx.x;
    if (tid == 0) s_is64 = 1;
    __syncthreads();
    if (tid < BATCH / 2) {
        long long v = ((const long long*)lab)[tid];
        if (v < 0 || v >= (long long)NCLS) s_is64 = 0;
    }
    __syncthreads();
    if (tid < BATCH) {
        int v;
        if (s_is64) v = (int)((const long long*)lab)[tid];
        else        v = ((const int*)lab)[tid];
        g_labels[tid] = v;
    }
}

// ---------------- per-call init ----------------
__global__ void k_init() {
    int t = threadIdx.x;
    g_sumB[t] = 0.0f;
    g_maxB[t] = 0ull;
}

// ---------------- x: norms, margin params, fp32 + fp8 normalize ----------------
__global__ void k_prep_x(const float* __restrict__ x) {
    int row = blockIdx.x;
    int t = threadIdx.x;  // 128
    float4 v = ((const float4*)(x + (size_t)row * DIM))[t];
    float ss = v.x * v.x + v.y * v.y + v.z * v.z + v.w * v.w;
    #pragma unroll
    for (int o = 16; o; o >>= 1) ss += __shfl_xor_sync(0xffffffffu, ss, o);
    __shared__ float s[4];
    if ((t & 31) == 0) s[t >> 5] = ss;
    __syncthreads();
    float tot = s[0] + s[1] + s[2] + s[3];
    float nrm = sqrtf(tot);
    float inv = 1.0f / nrm;
    if (t == 0) {
        float a = fminf(fmaxf(nrm, N_L), N_U);
        float m = (M_U - M_L) / (N_U - N_L) * (a - N_L) + M_L;
        g_mp[row] = make_float4(cosf(m), sinf(m), cosf(PI_F - m), sinf(PI_F - m) * m);
        g_xnorm_cl[row] = a;
    }
    float f0 = v.x * inv, f1 = v.y * inv, f2 = v.z * inv, f3 = v.w * inv;
    ((float4*)(g_xnf + (size_t)row * DIM))[t] = make_float4(f0, f1, f2, f3);
    unsigned short lo = cvt_e4m3x2(f1, f0);
    unsigned short hi = cvt_e4m3x2(f3, f2);
    ((uint32_t*)(g_xq + (size_t)row * DIM))[t] = (uint32_t)lo | ((uint32_t)hi << 16);
}

// ---------------- exact fp32 target-class logit (one block per sample) ----------------
__global__ void k_target(const float* __restrict__ W) {
    int b = blockIdx.x;
    int t = threadIdx.x;  // 128
    int lab = g_labels[b];
    float4 wv = ((const float4*)(W + (size_t)lab * DIM))[t];
    float4 xv = ((const float4*)(g_xnf + (size_t)b * DIM))[t];
    float dot = wv.x * xv.x + wv.y * xv.y + wv.z * xv.z + wv.w * xv.w;
    float ssq = wv.x * wv.x + wv.y * wv.y + wv.z * wv.z + wv.w * wv.w;
    #pragma unroll
    for (int o = 16; o; o >>= 1) {
        dot += __shfl_xor_sync(0xffffffffu, dot, o);
        ssq += __shfl_xor_sync(0xffffffffu, ssq, o);
    }
    __shared__ float sd[4], sq[4];
    if ((t & 31) == 0) { sd[t >> 5] = dot; sq[t >> 5] = ssq; }
    __syncthreads();
    if (t == 0) {
        float d = sd[0] + sd[1] + sd[2] + sd[3];
        float q = sq[0] + sq[1] + sq[2] + sq[3];
        float cs = d * rsqrtf(q);
        float4 mp = g_mp[b];
        float sine = sqrtf(fmaxf(0.0f, 1.0f - cs * cs));
        float phi = cs * mp.x - sine * mp.y;
        g_tlogit[b] = ((cs - mp.z > 0.0f) ? phi : (cs - mp.w)) * S_SCALE;
    }
}

// ---------------- FP8 fused GEMM + margin/softmax partials ----------------
// CTA: 64 classes (M) x 512 batch (N), K=512 in 4 chunks of 128.
// 512 threads = 16 warps as 2(M) x 8(N); warp tile 32x64;
// mma.sync.m16n8k32 e4m3; W fp32 streamed once (x64 -> e4m3, ||row||^2 in-flight).
__global__ void __launch_bounds__(512, 1) k_gemm(const float* __restrict__ W) {
    extern __shared__ char smem[];
    uint8_t* sX = (uint8_t*)(smem + OFF_SX);
    uint8_t* sW = (uint8_t*)(smem + OFF_SW);
    float* s_invn = (float*)(smem + OFF_INVN);
    float* s_rsum = (float*)(smem + OFF_RSUM);
    unsigned long long* s_rmax = (unsigned long long*)(smem + OFF_RMAX);
    int* s_lab = (int*)(smem + OFF_LAB);
    float* s_tl = (float*)(smem + OFF_TL);

    int tid = threadIdx.x;
    int ctile = blockIdx.x;
    int cbase = ctile * CM;

    s_lab[tid] = g_labels[tid];
    s_tl[tid] = g_tlogit[tid];

    uint32_t sx_u = (uint32_t)__cvta_generic_to_shared(sX);
    uint32_t sw_u = (uint32_t)__cvta_generic_to_shared(sW);

    // ---- W geometry: 8 threads per class row, 16 floats each per chunk ----
    int wrow = tid >> 3, och = tid & 7;
    bool wv = (cbase + wrow) < NCLS;
    const float* wp = W + (size_t)(wv ? cbase + wrow : 0) * DIM + och * 16;
    float ssq = 0.0f;
    float4 w4[4];

    int warp = tid >> 5, lane = tid & 31;
    int wm = warp & 1;        // M half (0..1)
    int wn = warp >> 1;       // N eighth (0..7)
    int g = lane >> 2, tg = lane & 3;

    // ldmatrix per-thread source geometry
    int a_lrow = wm * 32 + (lane & 7) + ((lane >> 3) & 1) * 8;   // + mt*16
    int a_lkb  = (lane >> 4) * 16;                                // k-byte offset
    int b_lrow = wn * 64 + (lane & 7) + (lane >> 4) * 8;          // + p*16
    int b_lkb  = ((lane >> 3) & 1) * 16;

    float acc[2][8][4];
    #pragma unroll
    for (int mt = 0; mt < 2; mt++)
        #pragma unroll
        for (int nt = 0; nt < 8; nt++)
            #pragma unroll
            for (int e = 0; e < 4; e++) acc[mt][nt][e] = 0.0f;

    // ---- prologue: B chunk 0 via cp.async, W chunk 0 into regs ----
    {
        #pragma unroll
        for (int j = 0; j < 8; j++) {
            int idx = tid + j * 512;
            int r = idx >> 3, ch = idx & 7;
            cpa16(sx_u + (uint32_t)(r * PITCHB + ch * 16), g_xq + (size_t)r * DIM + ch * 16);
        }
        asm volatile("cp.async.commit_group;");
        #pragma unroll
        for (int i = 0; i < 4; i++)
            w4[i] = ((const float4*)wp)[i];
    }

    #pragma unroll
    for (int c = 0; c < NCH; c++) {
        int cur = c & 1;
        asm volatile("cp.async.wait_group 0;" ::: "memory");
        // W regs: scale x64, ssq, convert to e4m3, one 16B STS
        {
            uint32_t h[4];
            #pragma unroll
            for (int i = 0; i < 4; i++) {
                float a = w4[i].x * WSC, b = w4[i].y * WSC;
                float cc = w4[i].z * WSC, d = w4[i].w * WSC;
                ssq += a * a + b * b + cc * cc + d * d;
                unsigned short lo = cvt_e4m3x2(b, a);
                unsigned short hi = cvt_e4m3x2(d, cc);
                h[i] = (uint32_t)lo | ((uint32_t)hi << 16);
            }
            *(uint4*)(sW + cur * (CM * PITCHB) + wrow * PITCHB + och * 16) =
                make_uint4(h[0], h[1], h[2], h[3]);
        }
        __syncthreads();

        if (c + 1 < NCH) {
            int kk = (c + 1) * BKK;
            uint32_t bbuf = sx_u + (uint32_t)((cur ^ 1) * (512 * PITCHB));
            #pragma unroll
            for (int j = 0; j < 8; j++) {
                int idx = tid + j * 512;
                int r = idx >> 3, ch = idx & 7;
                cpa16(bbuf + (uint32_t)(r * PITCHB + ch * 16),
                      g_xq + (size_t)r * DIM + kk + ch * 16);
            }
            asm volatile("cp.async.commit_group;");
            #pragma unroll
            for (int i = 0; i < 4; i++)
                w4[i] = ((const float4*)(wp + kk))[i];
        }

        uint32_t Abase = sw_u + (uint32_t)(cur * (CM * PITCHB));
        uint32_t Bbase = sx_u + (uint32_t)(cur * (512 * PITCHB));
        #pragma unroll
        for (int ks = 0; ks < 4; ks++) {      // 4 k-steps of 32
            unsigned af[2][4];
            #pragma unroll
            for (int mt = 0; mt < 2; mt++)
                ldsm_x4(Abase + (uint32_t)((a_lrow + mt * 16) * PITCHB + ks * 32 + a_lkb),
                        af[mt][0], af[mt][1], af[mt][2], af[mt][3]);
            #pragma unroll
            for (int p = 0; p < 4; p++) {
                unsigned b0, b1, b2, b3;
                ldsm_x4(Bbase + (uint32_t)((b_lrow + p * 16) * PITCHB + ks * 32 + b_lkb),
                        b0, b1, b2, b3);
                #pragma unroll
                for (int mt = 0; mt < 2; mt++) {
                    asm volatile(
                        "mma.sync.aligned.m16n8k32.row.col.f32.e4m3.e4m3.f32 "
                        "{%0,%1,%2,%3},{%4,%5,%6,%7},{%8,%9},{%0,%1,%2,%3};\n"
                        : "+f"(acc[mt][2 * p][0]), "+f"(acc[mt][2 * p][1]),
                          "+f"(acc[mt][2 * p][2]), "+f"(acc[mt][2 * p][3])
                        : "r"(af[mt][0]), "r"(af[mt][1]), "r"(af[mt][2]), "r"(af[mt][3]),
                          "r"(b0), "r"(b1));
                    asm volatile(
                        "mma.sync.aligned.m16n8k32.row.col.f32.e4m3.e4m3.f32 "
                        "{%0,%1,%2,%3},{%4,%5,%6,%7},{%8,%9},{%0,%1,%2,%3};\n"
                        : "+f"(acc[mt][2 * p + 1][0]), "+f"(acc[mt][2 * p + 1][1]),
                          "+f"(acc[mt][2 * p + 1][2]), "+f"(acc[mt][2 * p + 1][3])
                        : "r"(af[mt][0]), "r"(af[mt][1]), "r"(af[mt][2]), "r"(af[mt][3]),
                          "r"(b2), "r"(b3));
                }
            }
        }
    }

    // ---- ||64W||^2 reduce across 8 threads/row -> invn (fp32-exact) ----
    ssq += __shfl_xor_sync(0xffffffffu, ssq, 1);
    ssq += __shfl_xor_sync(0xffffffffu, ssq, 2);
    ssq += __shfl_xor_sync(0xffffffffu, ssq, 4);
    if (och == 0) s_invn[wrow] = (wv && ssq > 0.f) ? rsqrtf(ssq) : 0.f;
    __syncthreads();

    float invn_r[2][2];
    #pragma unroll
    for (int mt = 0; mt < 2; mt++)
        #pragma unroll
        for (int hi = 0; hi < 2; hi++)
            invn_r[mt][hi] = s_invn[wm * 32 + mt * 16 + g + hi * 8];

    // ---- fused epilogue ----
    #pragma unroll
    for (int nt = 0; nt < 8; nt++) {
        #pragma unroll
        for (int lo = 0; lo < 2; lo++) {
            int lcol = wn * 64 + nt * 8 + 2 * tg + lo;
            int lab = s_lab[lcol];
            float tl = s_tl[lcol];
            float lsum = 0.0f;
            unsigned long long lmax = 0ull;
            #pragma unroll
            for (int mt = 0; mt < 2; mt++) {
                #pragma unroll
                for (int hi = 0; hi < 2; hi++) {
                    int ccls = cbase + wm * 32 + mt * 16 + g + hi * 8;
                    if (ccls < NCLS) {
                        float v = acc[mt][nt][hi * 2 + lo] * invn_r[mt][hi];
                        float logit = (ccls == lab) ? tl : v * S_SCALE;
                        lsum += __expf(logit - SHIFT);
                        unsigned long long pk =
                            ((unsigned long long)fenc(logit) << 32) |
                            (unsigned long long)(0xFFFFFFFFu - (unsigned)ccls);
                        lmax = (pk > lmax) ? pk : lmax;
                    }
                }
            }
            #pragma unroll
            for (int off = 4; off < 32; off <<= 1) {
                lsum += __shfl_xor_sync(0xffffffffu, lsum, off);
                unsigned long long o = __shfl_xor_sync(0xffffffffu, lmax, off);
                lmax = (o > lmax) ? o : lmax;
            }
            if (g == 0) {
                s_rsum[wm * 512 + lcol] = lsum;
                s_rmax[wm * 512 + lcol] = lmax;
            }
        }
    }
    __syncthreads();
    atomicAdd(&g_sumB[tid], s_rsum[tid] + s_rsum[512 + tid]);
    unsigned long long a = s_rmax[tid], b = s_rmax[512 + tid];
    atomicMax(&g_maxB[tid], (a > b) ? a : b);
}

// ---------------- final scalar outputs ----------------
__global__ void k_final(float* __restrict__ out, int out_size) {
    int b = threadIdx.x;  // 512
    float lse = logf(g_sumB[b]) + SHIFT;
    float ce = lse - g_tlogit[b];
    int pred = (int)(0xFFFFFFFFu - (unsigned)(g_maxB[b] & 0xFFFFFFFFull));
    float corr = (pred == g_labels[b]) ? 1.0f : 0.0f;
    float a = g_xnorm_cl[b];
    float gt = a / (N_U * N_U) + 1.0f / a;

    __shared__ float s1[512], s2[512], s3[512];
    s1[b] = ce; s2[b] = corr; s3[b] = gt;
    __syncthreads();
    for (int o = 256; o; o >>= 1) {
        if (b < o) { s1[b] += s1[b + o]; s2[b] += s2[b + o]; s3[b] += s3[b + o]; }
        __syncthreads();
    }
    if (b == 0) {
        float loss = s1[0] / (float)BATCH + LAMBDA_G * (s3[0] / (float)BATCH);
        if (out_size >= 1) out[0] = loss;
        if (out_size >= 2) out[1] = s2[0] / (float)BATCH * 100.0f;
    }
    if (b >= 2 && b < out_size) out[b] = 0.0f;
}

extern "C" void kernel_launch(void* const* d_in, const int* in_sizes, int n_in,
                              void* d_out, int out_size) {
    const float* x = (const float*)d_in[0];
    const void* lab = d_in[1];
    const float* w = (const float*)d_in[2];
    (void)in_sizes; (void)n_in;

    cudaFuncSetAttribute(k_gemm, cudaFuncAttributeMaxDynamicSharedMemorySize, SMEM_BYTES);

    k_labels<<<1, 512>>>(lab);
    k_init<<<1, 512>>>();
    k_prep_x<<<BATCH, 128>>>(x);
    k_target<<<BATCH, 128>>>(w);
    k_gemm<<<NT, 512, SMEM_BYTES>>>(w);
    k_final<<<1, 512>>>((float*)d_out, out_size);
}

// round 8
// speedup vs baseline: 1.9995x; 1.0955x over previous
#include <cuda_runtime.h>
#include <cuda_bf16.h>
#include <math.h>
#include <stdint.h>

#define BATCH    512
#define NCLS     100000
#define DIM      512
#define CM       64                 /* classes per tile */
#define TILES    1563               /* ceil(NCLS/64) */
#define CPAD     (TILES * CM)       /* 100032 padded class rows */
#define HB       256                /* batch rows per CTA (half) */
#define STRIPS   74                 /* CTAs per half -> 148 total, one wave */
#define S_SCALE  30.0f
#define SHIFT    30.0f
#define N_U      110.0f
#define N_L      10.0f
#define M_U      1.0f
#define M_L      0.1f
#define LAMBDA_G 35.0f
#define PI_F     3.14159265358979323846f
#define WSC      64.0f              /* W pre-scale before e4m3 */

#define PITCH    528                /* smem row pitch bytes (512+16): 16B-shift/row mod 128 */
#define WBUF     (CM * PITCH)       /* 33792 per W buffer */

/* dynamic smem layout (bytes) */
#define OFF_SX    0                         /* 256 x 528 = 135168 */
#define OFF_SW    135168                    /* 2 x 64 x 528 = 67584 */
#define OFF_RSUM  202752                    /* float[2][256] = 2048 */
#define OFF_RMAX  204800                    /* ull[2][256]   = 4096 */
#define OFF_LAB   208896                    /* int[256]      = 1024 */
#define OFF_TL    209920                    /* float[256]    = 1024 */
#define SMEM_BYTES 210944

// ---------------- static device scratch ----------------
__device__ uint8_t g_wq[(size_t)CPAD * DIM];  // W e4m3 (51 MB; pad rows stay zero)
__device__ float   g_invn[CPAD];              // 1/||64*W_row|| (pad rows zero)
__device__ uint8_t g_xq[BATCH * DIM];         // x-hat e4m3
__device__ float   g_xnf[BATCH * DIM];        // x-hat fp32 (exact target dot)
__device__ float4  g_mp[BATCH];
__device__ float   g_xnorm_cl[BATCH];
__device__ float   g_tlogit[BATCH];
__device__ int     g_labels[BATCH];
__device__ float   g_sumB[BATCH];
__device__ unsigned long long g_maxB[BATCH];

__device__ __forceinline__ unsigned int fenc(float f) {
    unsigned int u = __float_as_uint(f);
    return (u & 0x80000000u) ? ~u : (u | 0x80000000u);
}
__device__ __forceinline__ unsigned short cvt_e4m3x2(float hi, float lo) {
    unsigned short r;
    asm("cvt.rn.satfinite.e4m3x2.f32 %0, %1, %2;" : "=h"(r) : "f"(hi), "f"(lo));
    return r;
}
__device__ __forceinline__ void cpa16(uint32_t dst, const void* src) {
    asm volatile("cp.async.cg.shared.global [%0], [%1], 16;" :: "r"(dst), "l"(src));
}
__device__ __forceinline__ void ldsm_x4(uint32_t addr, unsigned& r0, unsigned& r1,
                                        unsigned& r2, unsigned& r3) {
    asm volatile("ldmatrix.sync.aligned.m8n8.x4.shared.b16 {%0,%1,%2,%3}, [%4];"
                 : "=r"(r0), "=r"(r1), "=r"(r2), "=r"(r3) : "r"(addr));
}

// ---------------- label dtype detection + decode ----------------
__global__ void k_labels(const void* lab) {
    __shared__ int s_is64;
    int tid = threadIdx.x;
    if (tid == 0) s_is64 = 1;
    __syncthreads();
    if (tid < BATCH / 2) {
        long long v = ((const long long*)lab)[tid];
        if (v < 0 || v >= (long long)NCLS) s_is64 = 0;
    }
    __syncthreads();
    if (tid < BATCH) {
        int v;
        if (s_is64) v = (int)((const long long*)lab)[tid];
        else        v = ((const int*)lab)[tid];
        g_labels[tid] = v;
    }
}

__global__ void k_init() {
    int t = threadIdx.x;
    g_sumB[t] = 0.0f;
    g_maxB[t] = 0ull;
}

// ---------------- x: norms, margin params, fp32 + fp8 normalize ----------------
__global__ void k_prep_x(const float* __restrict__ x) {
    int row = blockIdx.x;
    int t = threadIdx.x;  // 128
    float4 v = ((const float4*)(x + (size_t)row * DIM))[t];
    float ss = v.x * v.x + v.y * v.y + v.z * v.z + v.w * v.w;
    #pragma unroll
    for (int o = 16; o; o >>= 1) ss += __shfl_xor_sync(0xffffffffu, ss, o);
    __shared__ float s[4];
    if ((t & 31) == 0) s[t >> 5] = ss;
    __syncthreads();
    float tot = s[0] + s[1] + s[2] + s[3];
    float nrm = sqrtf(tot);
    float inv = 1.0f / nrm;
    if (t == 0) {
        float a = fminf(fmaxf(nrm, N_L), N_U);
        float m = (M_U - M_L) / (N_U - N_L) * (a - N_L) + M_L;
        g_mp[row] = make_float4(cosf(m), sinf(m), cosf(PI_F - m), sinf(PI_F - m) * m);
        g_xnorm_cl[row] = a;
    }
    float f0 = v.x * inv, f1 = v.y * inv, f2 = v.z * inv, f3 = v.w * inv;
    ((float4*)(g_xnf + (size_t)row * DIM))[t] = make_float4(f0, f1, f2, f3);
    unsigned short lo = cvt_e4m3x2(f1, f0);
    unsigned short hi = cvt_e4m3x2(f3, f2);
    ((uint32_t*)(g_xq + (size_t)row * DIM))[t] = (uint32_t)lo | ((uint32_t)hi << 16);
}

// ---------------- exact fp32 target-class logit ----------------
__global__ void k_target(const float* __restrict__ W) {
    int b = blockIdx.x;
    int t = threadIdx.x;  // 128
    int lab = g_labels[b];
    float4 wv = ((const float4*)(W + (size_t)lab * DIM))[t];
    float4 xv = ((const float4*)(g_xnf + (size_t)b * DIM))[t];
    float dot = wv.x * xv.x + wv.y * xv.y + wv.z * xv.z + wv.w * xv.w;
    float ssq = wv.x * wv.x + wv.y * wv.y + wv.z * wv.z + wv.w * wv.w;
    #pragma unroll
    for (int o = 16; o; o >>= 1) {
        dot += __shfl_xor_sync(0xffffffffu, dot, o);
        ssq += __shfl_xor_sync(0xffffffffu, ssq, o);
    }
    __shared__ float sd[4], sq[4];
    if ((t & 31) == 0) { sd[t >> 5] = dot; sq[t >> 5] = ssq; }
    __syncthreads();
    if (t == 0) {
        float d = sd[0] + sd[1] + sd[2] + sd[3];
        float q = sq[0] + sq[1] + sq[2] + sq[3];
        float cs = d * rsqrtf(q);
        float4 mp = g_mp[b];
        float sine = sqrtf(fmaxf(0.0f, 1.0f - cs * cs));
        float phi = cs * mp.x - sine * mp.y;
        g_tlogit[b] = ((cs - mp.z > 0.0f) ? phi : (cs - mp.w)) * S_SCALE;
    }
}

// ---------------- W fp32 -> e4m3 (+ exact invn) : one pass, 205 MB read ----------------
__global__ void k_convw(const float* __restrict__ W) {
    int row = blockIdx.x * 8 + (threadIdx.x >> 5);
    if (row >= NCLS) return;
    int lane = threadIdx.x & 31;
    const float4* src = (const float4*)(W + (size_t)row * DIM) + lane * 4;
    float ssq = 0.0f;
    uint32_t h[4];
    #pragma unroll
    for (int i = 0; i < 4; i++) {
        float4 v = src[i];
        float a = v.x * WSC, b = v.y * WSC, c = v.z * WSC, d = v.w * WSC;
        ssq += a * a + b * b + c * c + d * d;
        unsigned short lo = cvt_e4m3x2(b, a);
        unsigned short hi = cvt_e4m3x2(d, c);
        h[i] = (uint32_t)lo | ((uint32_t)hi << 16);
    }
    *(uint4*)(g_wq + (size_t)row * DIM + lane * 16) = make_uint4(h[0], h[1], h[2], h[3]);
    #pragma unroll
    for (int o = 16; o; o >>= 1) ssq += __shfl_xor_sync(0xffffffffu, ssq, o);
    if (lane == 0) g_invn[row] = (ssq > 0.f) ? rsqrtf(ssq) : 0.f;
}

// ---------------- persistent-strip FP8 GEMM, x-hat resident ----------------
// Grid (74, 2): strip x batch-half. CTA: x-hat half (256x512 fp8) resident in smem,
// then ~21 class tiles of 64, W fp8 tile double-buffered via cp.async.
// 512 threads = 16 warps as 2(M) x 8(N); warp tile 32x32; mma.m16n8k32.e4m3.
__global__ void __launch_bounds__(512, 1) k_gemm() {
    extern __shared__ char smem[];
    uint32_t sbase = (uint32_t)__cvta_generic_to_shared(smem);
    uint32_t sx_u = sbase + OFF_SX;
    uint32_t sw_u = sbase + OFF_SW;
    float* s_rsum = (float*)(smem + OFF_RSUM);
    unsigned long long* s_rmax = (unsigned long long*)(smem + OFF_RMAX);
    int* s_lab = (int*)(smem + OFF_LAB);
    float* s_tl = (float*)(smem + OFF_TL);

    int tid = threadIdx.x;
    int strip = blockIdx.x, half = blockIdx.y;
    int hbase = half * HB;

    if (tid < HB) {
        s_lab[tid] = g_labels[hbase + tid];
        s_tl[tid] = g_tlogit[hbase + tid];
    }

    // ---- resident x-hat load: 256 rows x 512B, 16 x 16B per thread ----
    #pragma unroll
    for (int j = 0; j < 16; j++) {
        int idx = tid + j * 512;
        int r = idx >> 5, ch = idx & 31;
        cpa16(sx_u + (uint32_t)(r * PITCH + ch * 16),
              g_xq + (size_t)(hbase + r) * DIM + ch * 16);
    }
    asm volatile("cp.async.commit_group;");

    // ---- first W tile -> buf 0: 64 rows x 512B, 4 x 16B per thread ----
    {
        int t0 = strip;
        #pragma unroll
        for (int j = 0; j < 4; j++) {
            int idx = tid + j * 512;
            int r = idx >> 5, ch = idx & 31;
            cpa16(sw_u + (uint32_t)(r * PITCH + ch * 16),
                  g_wq + (size_t)(t0 * CM + r) * DIM + ch * 16);
        }
        asm volatile("cp.async.commit_group;");
    }
    asm volatile("cp.async.wait_group 0;" ::: "memory");
    __syncthreads();

    int warp = tid >> 5, lane = tid & 31;
    int wm = warp & 1;        // M half (0..1) of 64 classes
    int wn = warp >> 1;       // N eighth (0..7) of 256 batch
    int g = lane >> 2, tg = lane & 3;

    int a_lrow = wm * 32 + (lane & 7) + ((lane >> 3) & 1) * 8;   // + mt*16
    int a_lkb  = (lane >> 4) * 16;
    int b_lrow = wn * 32 + (lane & 7) + (lane >> 4) * 8;          // + p*16
    int b_lkb  = ((lane >> 3) & 1) * 16;

    int cur = 0;
    for (int t = strip; t < TILES; t += STRIPS) {
        // prefetch next W tile into buf cur^1 (overlaps with this tile's MMA)
        int tn = t + STRIPS;
        if (tn < TILES) {
            uint32_t wb = sw_u + (uint32_t)((cur ^ 1) * WBUF);
            #pragma unroll
            for (int j = 0; j < 4; j++) {
                int idx = tid + j * 512;
                int r = idx >> 5, ch = idx & 31;
                cpa16(wb + (uint32_t)(r * PITCH + ch * 16),
                      g_wq + (size_t)(tn * CM + r) * DIM + ch * 16);
            }
        }
        asm volatile("cp.async.commit_group;");

        float acc[2][4][4];
        #pragma unroll
        for (int mt = 0; mt < 2; mt++)
            #pragma unroll
            for (int nt = 0; nt < 4; nt++)
                #pragma unroll
                for (int e = 0; e < 4; e++) acc[mt][nt][e] = 0.0f;

        uint32_t Abase = sw_u + (uint32_t)(cur * WBUF);
        #pragma unroll
        for (int c = 0; c < 4; c++) {
            #pragma unroll
            for (int ks = 0; ks < 4; ks++) {
                int kb = c * 128 + ks * 32;
                unsigned af[2][4];
                #pragma unroll
                for (int mt = 0; mt < 2; mt++)
                    ldsm_x4(Abase + (uint32_t)((a_lrow + mt * 16) * PITCH + kb + a_lkb),
                            af[mt][0], af[mt][1], af[mt][2], af[mt][3]);
                #pragma unroll
                for (int p = 0; p < 2; p++) {
                    unsigned b0, b1, b2, b3;
                    ldsm_x4(sx_u + (uint32_t)((b_lrow + p * 16) * PITCH + kb + b_lkb),
                            b0, b1, b2, b3);
                    #pragma unroll
                    for (int mt = 0; mt < 2; mt++) {
                        asm volatile(
                            "mma.sync.aligned.m16n8k32.row.col.f32.e4m3.e4m3.f32 "
                            "{%0,%1,%2,%3},{%4,%5,%6,%7},{%8,%9},{%0,%1,%2,%3};\n"
                            : "+f"(acc[mt][2 * p][0]), "+f"(acc[mt][2 * p][1]),
                              "+f"(acc[mt][2 * p][2]), "+f"(acc[mt][2 * p][3])
                            : "r"(af[mt][0]), "r"(af[mt][1]), "r"(af[mt][2]), "r"(af[mt][3]),
                              "r"(b0), "r"(b1));
                        asm volatile(
                            "mma.sync.aligned.m16n8k32.row.col.f32.e4m3.e4m3.f32 "
                            "{%0,%1,%2,%3},{%4,%5,%6,%7},{%8,%9},{%0,%1,%2,%3};\n"
                            : "+f"(acc[mt][2 * p + 1][0]), "+f"(acc[mt][2 * p + 1][1]),
                              "+f"(acc[mt][2 * p + 1][2]), "+f"(acc[mt][2 * p + 1][3])
                            : "r"(af[mt][0]), "r"(af[mt][1]), "r"(af[mt][2]), "r"(af[mt][3]),
                              "r"(b2), "r"(b3));
                    }
                }
            }
        }

        // ---- tile epilogue ----
        float invn_r[2][2];
        #pragma unroll
        for (int mt = 0; mt < 2; mt++)
            #pragma unroll
            for (int hi = 0; hi < 2; hi++)
                invn_r[mt][hi] = g_invn[t * CM + wm * 32 + mt * 16 + g + hi * 8];

        #pragma unroll
        for (int nt = 0; nt < 4; nt++) {
            #pragma unroll
            for (int lo = 0; lo < 2; lo++) {
                int lcol = wn * 32 + nt * 8 + 2 * tg + lo;     // 0..255
                int lab = s_lab[lcol];
                float tl = s_tl[lcol];
                float lsum = 0.0f;
                unsigned long long lmax = 0ull;
                #pragma unroll
                for (int mt = 0; mt < 2; mt++) {
                    #pragma unroll
                    for (int hi = 0; hi < 2; hi++) {
                        int ccls = t * CM + wm * 32 + mt * 16 + g + hi * 8;
                        if (ccls < NCLS) {
                            float v = acc[mt][nt][hi * 2 + lo] * invn_r[mt][hi];
                            float logit = (ccls == lab) ? tl : v * S_SCALE;
                            lsum += __expf(logit - SHIFT);
                            unsigned long long pk =
                                ((unsigned long long)fenc(logit) << 32) |
                                (unsigned long long)(0xFFFFFFFFu - (unsigned)ccls);
                            lmax = (pk > lmax) ? pk : lmax;
                        }
                    }
                }
                #pragma unroll
                for (int off = 4; off < 32; off <<= 1) {
                    lsum += __shfl_xor_sync(0xffffffffu, lsum, off);
                    unsigned long long o = __shfl_xor_sync(0xffffffffu, lmax, off);
                    lmax = (o > lmax) ? o : lmax;
                }
                if (g == 0) {
                    s_rsum[wm * HB + lcol] = lsum;
                    s_rmax[wm * HB + lcol] = lmax;
                }
            }
        }
        __syncthreads();
        if (tid < HB) {
            atomicAdd(&g_sumB[hbase + tid], s_rsum[tid] + s_rsum[HB + tid]);
            unsigned long long a = s_rmax[tid], b = s_rmax[HB + tid];
            atomicMax(&g_maxB[hbase + tid], (a > b) ? a : b);
        }
        asm volatile("cp.async.wait_group 0;" ::: "memory");
        __syncthreads();
        cur ^= 1;
    }
}

// ---------------- final scalar outputs ----------------
__global__ void k_final(float* __restrict__ out, int out_size) {
    int b = threadIdx.x;  // 512
    float lse = logf(g_sumB[b]) + SHIFT;
    float ce = lse - g_tlogit[b];
    int pred = (int)(0xFFFFFFFFu - (unsigned)(g_maxB[b] & 0xFFFFFFFFull));
    float corr = (pred == g_labels[b]) ? 1.0f : 0.0f;
    float a = g_xnorm_cl[b];
    float gt = a / (N_U * N_U) + 1.0f / a;

    __shared__ float s1[512], s2[512], s3[512];
    s1[b] = ce; s2[b] = corr; s3[b] = gt;
    __syncthreads();
    for (int o = 256; o; o >>= 1) {
        if (b < o) { s1[b] += s1[b + o]; s2[b] += s2[b + o]; s3[b] += s3[b + o]; }
        __syncthreads();
    }
    if (b == 0) {
        float loss = s1[0] / (float)BATCH + LAMBDA_G * (s3[0] / (float)BATCH);
        if (out_size >= 1) out[0] = loss;
        if (out_size >= 2) out[1] = s2[0] / (float)BATCH * 100.0f;
    }
    if (b >= 2 && b < out_size) out[b] = 0.0f;
}

extern "C" void kernel_launch(void* const* d_in, const int* in_sizes, int n_in,
                              void* d_out, int out_size) {
    const float* x = (const float*)d_in[0];
    const void* lab = d_in[1];
    const float* w = (const float*)d_in[2];
    (void)in_sizes; (void)n_in;

    cudaFuncSetAttribute(k_gemm, cudaFuncAttributeMaxDynamicSharedMemorySize, SMEM_BYTES);

    k_labels<<<1, 512>>>(lab);
    k_init<<<1, 512>>>();
    k_prep_x<<<BATCH, 128>>>(x);
    k_target<<<BATCH, 128>>>(w);
    k_convw<<<(NCLS + 7) / 8, 256>>>(w);
    dim3 grid(STRIPS, 2);
    k_gemm<<<grid, 512, SMEM_BYTES>>>();
    k_final<<<1, 512>>>((float*)d_out, out_size);
}